// round 17
// baseline (speedup 1.0000x reference)
#include <cuda_runtime.h>
#include <cstdint>
#include <cstddef>

// FPS: B=8, N=131072, NPOINT=1024 -> out [8,1024,3] fp32.
// R16 champion (1472.6us) with ONE surgical change: streamed-pair z values
// packed two-pairs-per-ulonglong2, so each 2 streamed pairs cost
// 3x LDS.128 (xy_a, xy_b, z_ab) instead of 2x LDS.128 + 2x LDS.64
// (-4 load slots/thread/step, register-neutral). Candidate fetch indexes
// packed z by (q>>1, q&1) -- same split-region pattern as R8/R16.
// Everything else byte-identical: 8 clusters x 8 CTAs x 512 thr; 16 pairs/
// thread (8 reg, 8 streamed); FFMA2 distance math; REDUX argmax (max dist,
// min index); coords ride the reduction -> DSMEM slots; ONE barrier.cluster
// per step; every warp reduces the 8 slots locally.

#define NB       8
#define NPTS     131072
#define NSAMP    1024
#define CSIZE    8
#define TPB      512
#define PPB      (NPTS / CSIZE)    // 16384 points per CTA
#define PAIRS    (PPB / 2)         // 8192 pairs per CTA
#define REGJ     8                 // pairs/thread in registers
#define TOTJ     16                // pairs/thread total
#define STRJ     (TOTJ - REGJ)     // 8 streamed pairs/thread
#define NPT      32                // points/thread
#define NWARPS   (TPB / 32)        // 16
#define APAIRS   (REGJ * TPB)      // 4096 pairs (register half, pair-major mirror)
#define BPAIRS   (STRJ * TPB)      // 4096 pairs (streamed half)
#define HZ       (STRJ / 2)        // 4 z-packs per thread

struct __align__(16) Red { unsigned v, i; float x, y, z; unsigned pad[3]; };  // 32B

struct Smem {
    Red warpred[NWARPS];
    Red slots[2][CSIZE];
    unsigned long long xa[APAIRS];   // register-half mirror (pair-major)
    unsigned long long ya[APAIRS];
    unsigned long long za[APAIRS];
    ulonglong2         xyb[BPAIRS];      // streamed: {x2, y2} per pair
    ulonglong2         zb2[HZ * TPB];    // streamed: {z2 of pair 2h, z2 of pair 2h+1}
};

// ---------- asm helpers ----------
__device__ __forceinline__ unsigned ctarank() {
    unsigned r; asm("mov.u32 %0, %%cluster_ctarank;" : "=r"(r)); return r;
}
__device__ __forceinline__ unsigned cvta_s(const void* p) {
    unsigned r;
    asm("{ .reg .u64 t; cvta.to.shared.u64 t, %1; cvt.u32.u64 %0, t; }"
        : "=r"(r) : "l"(p));
    return r;
}
__device__ __forceinline__ unsigned mapa_s(unsigned laddr, unsigned rank) {
    unsigned r;
    asm("mapa.shared::cluster.u32 %0, %1, %2;" : "=r"(r) : "r"(laddr), "r"(rank));
    return r;
}
__device__ __forceinline__ unsigned long long packf2(float lo, float hi) {
    unsigned long long r;
    asm("mov.b64 %0, {%1, %2};" : "=l"(r) : "f"(lo), "f"(hi));
    return r;
}
__device__ __forceinline__ void unpackf2(unsigned long long v, float& lo, float& hi) {
    asm("mov.b64 {%0, %1}, %2;" : "=f"(lo), "=f"(hi) : "l"(v));
}
__device__ __forceinline__ unsigned long long mulx2(unsigned long long a,
                                                    unsigned long long b) {
    unsigned long long r;
    asm("mul.rn.f32x2 %0, %1, %2;" : "=l"(r) : "l"(a), "l"(b));
    return r;
}
__device__ __forceinline__ unsigned long long fmx2(unsigned long long a,
                                                   unsigned long long b,
                                                   unsigned long long c) {
    unsigned long long r;
    asm("fma.rn.f32x2 %0, %1, %2, %3;" : "=l"(r) : "l"(a), "l"(b), "l"(c));
    return r;
}
__device__ __forceinline__ void st_cluster_v4(unsigned raddr, unsigned a, unsigned b,
                                              unsigned c, unsigned d) {
    asm volatile("st.shared::cluster.v4.b32 [%0], {%1,%2,%3,%4};"
                 :: "r"(raddr), "r"(a), "r"(b), "r"(c), "r"(d) : "memory");
}
__device__ __forceinline__ void st_cluster_u32(unsigned raddr, unsigned v) {
    asm volatile("st.shared::cluster.u32 [%0], %1;" :: "r"(raddr), "r"(v) : "memory");
}
__device__ __forceinline__ void cluster_bar() {
    asm volatile("barrier.cluster.arrive.aligned;" ::: "memory");
    asm volatile("barrier.cluster.wait.aligned;"   ::: "memory");
}

__global__ void __launch_bounds__(TPB, 1)
fps_kernel(const float* __restrict__ xyz, float* __restrict__ out) {
    extern __shared__ __align__(16) unsigned char smem_raw[];
    Smem* s = reinterpret_cast<Smem*>(smem_raw);

    const int      tid  = threadIdx.x;
    const unsigned lane = tid & 31;
    const unsigned warp = (unsigned)tid >> 5;
    const unsigned rank = ctarank();
    const int      batch = blockIdx.x / CSIZE;

    const float* __restrict__ base = xyz + (size_t)batch * NPTS * 3;
    const unsigned pbase = rank * PPB;

    // ---- load: reg pairs -> registers + pair-major mirror;
    //            streamed pairs -> interleaved xy + paired z ----
    unsigned long long X[REGJ], Y[REGJ], Z[REGJ];
#pragma unroll
    for (int j = 0; j < TOTJ; ++j) {
        unsigned P = (unsigned)j * TPB + (unsigned)tid;   // global pair id in CTA
        const float2* p = reinterpret_cast<const float2*>(
            base + (size_t)(pbase + 2u * P) * 3);
        float2 a = p[0];  // x0 y0
        float2 b = p[1];  // z0 x1
        float2 c = p[2];  // y1 z1
        unsigned long long px = packf2(a.x, b.y);
        unsigned long long py = packf2(a.y, c.x);
        unsigned long long pz = packf2(b.x, c.y);
        if (j < REGJ) {
            X[j] = px; Y[j] = py; Z[j] = pz;
            s->xa[P] = px; s->ya[P] = py; s->za[P] = pz;
        } else {
            unsigned q = (unsigned)(j - REGJ);
            s->xyb[q * TPB + (unsigned)tid] = make_ulonglong2(px, py);
            unsigned h = q >> 1;
            if (q & 1u) s->zb2[h * TPB + (unsigned)tid].y = pz;
            else        s->zb2[h * TPB + (unsigned)tid].x = pz;
        }
    }

    float m[NPT];
#pragma unroll
    for (int k = 0; k < NPT; ++k) m[k] = __int_as_float(0x7f800000);  // +inf

    // remote slot addresses for pushes (warp0 lanes < CSIZE), both parities
    unsigned rs0 = 0, rs1 = 0;
    if (warp == 0 && lane < CSIZE) {
        rs0 = mapa_s(cvta_s(&s->slots[0][rank]), lane);
        rs1 = mapa_s(cvta_s(&s->slots[1][rank]), lane);
    }

    // initial centroid = point 0 of this batch (broadcast L2 load, once)
    float cx = __ldg(base + 0);
    float cy = __ldg(base + 1);
    float cz = __ldg(base + 2);
    if (rank == 0 && tid == 0) {
        float* o = out + (size_t)batch * NSAMP * 3;
        o[0] = cx; o[1] = cy; o[2] = cz;
    }
    __syncthreads();   // smem ready

    const unsigned long long ONE2 = packf2(1.0f, 1.0f);

    for (int t = 1; t < NSAMP; ++t) {
        const unsigned long long ncx = packf2(-cx, -cx);
        const unsigned long long ncy = packf2(-cy, -cy);
        const unsigned long long ncz = packf2(-cz, -cz);

        float bm = -1.0f;

        // ---- register pairs (no LDS) ----
#pragma unroll
        for (int j = 0; j < REGJ; ++j) {
            unsigned long long dx = fmx2(X[j], ONE2, ncx);
            unsigned long long dy = fmx2(Y[j], ONE2, ncy);
            unsigned long long dz = fmx2(Z[j], ONE2, ncz);
            unsigned long long dd = mulx2(dx, dx);
            dd = fmx2(dy, dy, dd);
            dd = fmx2(dz, dz, dd);
            float d0, d1; unpackf2(dd, d0, d1);
            float m0 = fminf(m[2 * j], d0);
            float m1 = fminf(m[2 * j + 1], d1);
            m[2 * j] = m0; m[2 * j + 1] = m1;
            bm = fmaxf(bm, fmaxf(m0, m1));
        }
        // ---- streamed pairs: 3x LDS.128 per 2 pairs ----
#pragma unroll
        for (int h = 0; h < HZ; ++h) {
            ulonglong2 xyA = s->xyb[(2 * h + 0) * TPB + (unsigned)tid];
            ulonglong2 xyB = s->xyb[(2 * h + 1) * TPB + (unsigned)tid];
            ulonglong2 zz  = s->zb2[h * TPB + (unsigned)tid];
#pragma unroll
            for (int e = 0; e < 2; ++e) {
                const int j = REGJ + 2 * h + e;
                unsigned long long dx = fmx2(e ? xyB.x : xyA.x, ONE2, ncx);
                unsigned long long dy = fmx2(e ? xyB.y : xyA.y, ONE2, ncy);
                unsigned long long dz = fmx2(e ? zz.y  : zz.x,  ONE2, ncz);
                unsigned long long dd = mulx2(dx, dx);
                dd = fmx2(dy, dy, dd);
                dd = fmx2(dz, dz, dd);
                float d0, d1; unpackf2(dd, d0, d1);
                float m0 = fminf(m[2 * j], d0);
                float m1 = fminf(m[2 * j + 1], d1);
                m[2 * j] = m0; m[2 * j + 1] = m1;
                bm = fmaxf(bm, fmaxf(m0, m1));
            }
        }

        // ---- resolve smallest k with m[k]==bm (downward scan) ----
        int kk = 0;
#pragma unroll
        for (int k = NPT - 1; k >= 0; --k)
            if (m[k] == bm) kk = k;

        const unsigned jw   = (unsigned)kk >> 1;
        const unsigned Pw   = jw * TPB + (unsigned)tid;
        const unsigned gidx = pbase + 2u * Pw + (unsigned)(kk & 1);

        unsigned long long wx, wy, wz;
        if (jw < REGJ) {
            wx = s->xa[Pw]; wy = s->ya[Pw]; wz = s->za[Pw];
        } else {
            unsigned q = jw - REGJ;
            ulonglong2 xy = s->xyb[q * TPB + (unsigned)tid];
            ulonglong2 zz = s->zb2[(q >> 1) * TPB + (unsigned)tid];
            wx = xy.x; wy = xy.y;
            wz = (q & 1u) ? zz.y : zz.x;
        }
        float a0, a1, b0, b1, c0, c1;
        unpackf2(wx, a0, a1);
        unpackf2(wy, b0, b1);
        unpackf2(wz, c0, c1);
        float candx = (kk & 1) ? a1 : a0;
        float candy = (kk & 1) ? b1 : b0;
        float candz = (kk & 1) ? c1 : c0;

        // ---- warp reduce: max dist bits, then min index among maxima ----
        unsigned vb = __float_as_uint(bm);            // d>=0: int order == float order
        unsigned wv = __reduce_max_sync(0xffffffffu, vb);
        unsigned cd = (vb == wv) ? gidx : 0xffffffffu;
        unsigned wi = __reduce_min_sync(0xffffffffu, cd);
        if (cd == wi) {                               // unique winner lane stores
            *reinterpret_cast<uint4*>(&s->warpred[warp]) =
                make_uint4(wv, wi, __float_as_uint(candx), __float_as_uint(candy));
            s->warpred[warp].z = candz;
        }
        __syncthreads();

        const int par = t & 1;

        // ---- block reduce over 16 warp partials + push to all 8 peers ----
        if (warp == 0) {
            unsigned v = 0, i = 0xffffffffu, xb = 0, yb = 0, zb = 0;
            if (lane < NWARPS) {
                uint4 w = *reinterpret_cast<const uint4*>(&s->warpred[lane]);
                v = w.x; i = w.y; xb = w.z; yb = w.w;
                zb = __float_as_uint(s->warpred[lane].z);
            }
            unsigned bv = __reduce_max_sync(0xffffffffu, v);
            unsigned bc = (v == bv) ? i : 0xffffffffu;
            unsigned bi = __reduce_min_sync(0xffffffffu, bc);
            unsigned msk = __ballot_sync(0xffffffffu, bc == bi);
            int L = __ffs(msk) - 1;
            xb = __shfl_sync(0xffffffffu, xb, L);
            yb = __shfl_sync(0xffffffffu, yb, L);
            zb = __shfl_sync(0xffffffffu, zb, L);
            if (lane < CSIZE) {
                unsigned ra = par ? rs1 : rs0;
                st_cluster_v4(ra, bv, bi, xb, yb);
                st_cluster_u32(ra + 16, zb);
            }
        }

        // one cluster barrier per step (arrive releases the DSMEM stores)
        cluster_bar();

        // ---- EVERY warp reduces the 8 slots -> next centroid in registers ----
        {
            unsigned v = 0, i = 0xffffffffu, xb = 0, yb = 0, zb = 0;
            if (lane < CSIZE) {
                uint4 w = *reinterpret_cast<const uint4*>(&s->slots[par][lane]);
                v = w.x; i = w.y; xb = w.z; yb = w.w;
                zb = __float_as_uint(s->slots[par][lane].z);
            }
            unsigned cv = __reduce_max_sync(0xffffffffu, v);
            unsigned cc = (v == cv) ? i : 0xffffffffu;
            unsigned ci = __reduce_min_sync(0xffffffffu, cc);
            unsigned msk = __ballot_sync(0xffffffffu, cc == ci);
            int W = __ffs(msk) - 1;
            cx = __uint_as_float(__shfl_sync(0xffffffffu, xb, W));
            cy = __uint_as_float(__shfl_sync(0xffffffffu, yb, W));
            cz = __uint_as_float(__shfl_sync(0xffffffffu, zb, W));
            if (rank == 0 && tid == 0) {
                float* o = out + ((size_t)batch * NSAMP + (size_t)t) * 3;
                o[0] = cx; o[1] = cy; o[2] = cz;
            }
        }
        // warpred: each warp rewrites only its own entry after its own warp
        // stage; warp0 reads right after the block-wide __syncthreads.
        // slots: double-buffered by parity, protected by the cluster barrier.
    }

    cluster_bar();  // keep CTAs alive until all DSMEM traffic has landed
}

extern "C" void kernel_launch(void* const* d_in, const int* in_sizes, int n_in,
                              void* d_out, int out_size) {
    (void)in_sizes; (void)n_in; (void)out_size;
    const float* xyz = (const float*)d_in[0];
    float* out = (float*)d_out;

    cudaFuncSetAttribute(fps_kernel,
                         cudaFuncAttributeMaxDynamicSharedMemorySize,
                         (int)sizeof(Smem));

    cudaLaunchConfig_t cfg = {};
    cfg.gridDim  = dim3(NB * CSIZE, 1, 1);   // 64 CTAs
    cfg.blockDim = dim3(TPB, 1, 1);
    cfg.dynamicSmemBytes = sizeof(Smem);
    cfg.stream = 0;

    cudaLaunchAttribute attr[1];
    attr[0].id = cudaLaunchAttributeClusterDimension;
    attr[0].val.clusterDim.x = CSIZE;
    attr[0].val.clusterDim.y = 1;
    attr[0].val.clusterDim.z = 1;
    cfg.attrs = attr;
    cfg.numAttrs = 1;

    cudaLaunchKernelEx(&cfg, fps_kernel, xyz, out);
}